// round 12
// baseline (speedup 1.0000x reference)
#include <cuda_runtime.h>
#include <math.h>

// GibbsSampler — round 12: GLOBAL wave leveling + wave-sorted execution.
//
// level(i) = 1 + max level of ALL earlier conflicting positions in the sweep
// (conflict = Chebyshev <= 1; only the latest update per cell matters, so a
// persistent per-cell level grid Lg turns the chunked fixpoint into an
// incremental global leveler). Schedule depends only on perm => computed once,
// reused by both sweeps. Positions are counting-sorted by level into
// wave-contiguous arrays (site, r_sweep1, r_sweep2) so phase 2 is a clean
// per-wave loop: coalesced loads, 8 random LDS on the smem lattice, sample,
// store, one __syncthreads per wave (~gmax ~ 40 waves per sweep).
// Same-wave updates are pairwise non-conflicting => race-free.
//
// Numerics: bit-exact pipeline from rounds 7-11 (double-precision exp table,
// _rn mul/sub/add/div, sequential cumsum). OUTPUT IS FLOAT32.

#define NSITES 65536
#define NSWEEPS 2
#define BLOCK   1024
#define NCHUNK  64
#define LMAX    384          // level clamp (P(level > 60) ~ 0)

__device__ unsigned short d_lvl[NSITES];    // per-position global level
__device__ unsigned short d_site[NSITES];   // wave-sorted site
__device__ float          d_r1[NSITES];     // wave-sorted uniforms, sweep 1
__device__ float          d_r2[NSITES];     // wave-sorted uniforms, sweep 2

__global__ __launch_bounds__(BLOCK, 1)
void gibbs_glv(const unsigned int* __restrict__ A,   // X_init or perm
               const unsigned int* __restrict__ B,   // the other one
               const float* __restrict__ U,          // uniforms (2,65536)
               const unsigned int* __restrict__ s0,  // beta or K
               const unsigned int* __restrict__ s1,  // the other one
               float* __restrict__ out)              // FLOAT32 output
{
    extern __shared__ unsigned char dyn[];
    unsigned short* stamp = (unsigned short*)dyn;    // [0,131072): phase 1 only
    unsigned char*  Xs    = dyn;                     // overlays stamp in phase 2
    unsigned char*  Lg    = dyn + 131072;            // [131072,196608): cell levels

    __shared__ float4       s_B[729];
    __shared__ int          s_hist[LMAX + 2];
    __shared__ int          s_start[LMAX + 2];
    __shared__ int          s_off[LMAX + 2];
    __shared__ int          s_lv[BLOCK];
    __shared__ int          s_gmax;
    __shared__ unsigned int s_maxA, s_maxB;

    const int tid  = threadIdx.x;
    const int lane = tid & 31;

    // ---------- classify inputs ----------
    if (tid == 0) { s_maxA = 0u; s_maxB = 0u; s_gmax = 0; }
    __syncthreads();
    {
        const uint4* A4 = (const uint4*)A;
        const uint4* B4 = (const uint4*)B;
        unsigned int mA = 0u, mB = 0u;
        for (int i = tid; i < NSITES / 4; i += BLOCK) {
            uint4 a = __ldg(&A4[i]);
            uint4 b = __ldg(&B4[i]);
            mA = max(max(max(a.x, a.y), max(a.z, a.w)), mA);
            mB = max(max(max(b.x, b.y), max(b.z, b.w)), mB);
        }
        atomicMax(&s_maxA, mA);
        atomicMax(&s_maxB, mB);
    }
    __syncthreads();
    const int b_is_x = (s_maxB <= 3u) && (s_maxA > 3u);
    const unsigned int* Xw = b_is_x ? B : A;
    const unsigned int* Pw = b_is_x ? A : B;

    const unsigned int w0 = __ldg(s0);
    const unsigned int w1 = __ldg(s1);
    float beta;
    if (w0 == 4u)      beta = __uint_as_float(w1);
    else if (w1 == 4u) beta = __uint_as_float(w0);
    else if (w0 >= 0x3F000000u && w0 < 0x3FC00000u) beta = __uint_as_float(w0);
    else               beta = __uint_as_float(w1);

    // ---------- init: stamp sentinel, Lg=0, histogram, boundary table ----------
    for (int i = tid; i < NSITES; i += BLOCK) { stamp[i] = 0xFFFFu; Lg[i] = 0; }
    for (int t = tid; t <= LMAX + 1; t += BLOCK) s_hist[t] = 0;
    for (int t = tid; t < 729; t += BLOCK) {
        int c0 = t % 9, c1 = (t / 9) % 9, c2 = t / 81;
        int c3 = 8 - c0 - c1 - c2;
        if (c3 >= 0) {
            int cm = max(max(c0, c1), max(c2, c3));
            float bm = __fmul_rn(beta, (float)cm);
            float e0 = (float)exp((double)__fsub_rn(__fmul_rn(beta, (float)c0), bm));
            float e1 = (float)exp((double)__fsub_rn(__fmul_rn(beta, (float)c1), bm));
            float e2 = (float)exp((double)__fsub_rn(__fmul_rn(beta, (float)c2), bm));
            float e3 = (float)exp((double)__fsub_rn(__fmul_rn(beta, (float)c3), bm));
            float s  = __fadd_rn(__fadd_rn(__fadd_rn(e0, e1), e2), e3);
            float a0 = __fdiv_rn(e0, s);
            float a1 = __fadd_rn(a0, __fdiv_rn(e1, s));
            float a2 = __fadd_rn(a1, __fdiv_rn(e2, s));
            float a3 = __fadd_rn(a2, __fdiv_rn(e3, s));
            s_B[t] = make_float4(a0, a1, a2, a3);
        }
    }
    __syncthreads();

    // ---------- PHASE 1: global levels via incremental chunked fixpoint ----------
    for (int chunk = 0; chunk < NCHUNK; chunk++) {
        const int base = chunk << 10;
        const int site = (int)(__ldg(&Pw[base + tid]) & 0xFFFFu);
        const int u = site >> 8, v = site & 255;
        const int um = (u > 0)   ? u - 1 : 0;
        const int up = (u < 255) ? u + 1 : 255;
        const int vm = (v > 0)   ? v - 1 : 0;
        const int vp = (v < 255) ? v + 1 : 255;
        const int ra = um << 8, rb = u << 8, rc = up << 8;
        const int n0 = ra | vm, n1 = ra | v, n2 = ra | vp;
        const int n3 = rb | vm,              n4 = rb | vp;
        const int n5 = rc | vm, n6 = rc | v, n7 = rc | vp;

        stamp[site] = (unsigned short)tid;
        __syncthreads();

        // in-chunk deps (earlier chunk positions in my box) + pre-chunk base
        int d0 = (int)stamp[n0], d1 = (int)stamp[n1];
        int d2 = (int)stamp[n2], d3 = (int)stamp[n3];
        int d4 = (int)stamp[n4], d5 = (int)stamp[n5];
        int d6 = (int)stamp[n6], d7 = (int)stamp[n7];
        if (d0 >= tid) d0 = -1;  if (d1 >= tid) d1 = -1;
        if (d2 >= tid) d2 = -1;  if (d3 >= tid) d3 = -1;
        if (d4 >= tid) d4 = -1;  if (d5 >= tid) d5 = -1;
        if (d6 >= tid) d6 = -1;  if (d7 >= tid) d7 = -1;
        int bl = max(max(max((int)Lg[n0], (int)Lg[n1]),
                         max((int)Lg[n2], (int)Lg[n3])),
                     max(max((int)Lg[n4], (int)Lg[n5]),
                         max((int)Lg[n6], (int)Lg[n7])));
        const int ndep = (d0 >= 0) + (d1 >= 0) + (d2 >= 0) + (d3 >= 0) +
                         (d4 >= 0) + (d5 >= 0) + (d6 >= 0) + (d7 >= 0);
        int myl = (ndep == 0) ? bl + 1 : 0;
        s_lv[tid] = myl;
        __syncthreads();   // all reads of stamp/Lg done; s_lv inits visible

        // fixpoint: myl = 1 + max(bl, in-chunk dep levels)
        for (;;) {
            if (!myl) {
                int ok = 1, mx = bl, l;
                if (d0 >= 0) { l = s_lv[d0]; ok &= (l != 0); mx = max(mx, l); }
                if (d1 >= 0) { l = s_lv[d1]; ok &= (l != 0); mx = max(mx, l); }
                if (d2 >= 0) { l = s_lv[d2]; ok &= (l != 0); mx = max(mx, l); }
                if (d3 >= 0) { l = s_lv[d3]; ok &= (l != 0); mx = max(mx, l); }
                if (d4 >= 0) { l = s_lv[d4]; ok &= (l != 0); mx = max(mx, l); }
                if (d5 >= 0) { l = s_lv[d5]; ok &= (l != 0); mx = max(mx, l); }
                if (d6 >= 0) { l = s_lv[d6]; ok &= (l != 0); mx = max(mx, l); }
                if (d7 >= 0) { l = s_lv[d7]; ok &= (l != 0); mx = max(mx, l); }
                if (ok) { myl = mx + 1; s_lv[tid] = myl; }
            }
            if (__syncthreads_count(myl == 0) == 0) break;
        }

        // commit: cell level, position level, histogram, stamp clear
        int mc = min(myl, LMAX);
        Lg[site] = (unsigned char)min(myl, 255);
        d_lvl[base + tid] = (unsigned short)mc;
        atomicAdd(&s_hist[mc], 1);
        stamp[site] = 0xFFFFu;
        int wm = __reduce_max_sync(0xFFFFFFFFu, mc);
        if (lane == 0) atomicMax(&s_gmax, wm);
        __syncthreads();
    }

    // ---------- prefix sum over levels ----------
    if (tid == 0) {
        int acc = 0;
        for (int w = 1; w <= LMAX; w++) { s_start[w] = acc; acc += s_hist[w]; }
        s_start[LMAX + 1] = acc;
    }
    __syncthreads();
    for (int t = tid; t <= LMAX + 1; t += BLOCK) s_off[t] = (t <= LMAX) ? s_start[t] : 0;
    __syncthreads();

    // ---------- counting-sort scatter (coalesced reads, scattered writes) ----------
    for (int pos = tid; pos < NSITES; pos += BLOCK) {
        int lv = (int)d_lvl[pos];
        int st = (int)(__ldg(&Pw[pos]) & 0xFFFFu);
        float r1 = __ldg(&U[pos]);
        float r2 = __ldg(&U[NSITES + pos]);
        unsigned m = __match_any_sync(0xFFFFFFFFu, lv);
        int leader = __ffs(m) - 1;
        int rank = __popc(m & ((1u << lane) - 1u));
        int bslot = 0;
        if (lane == leader) bslot = atomicAdd(&s_off[lv], __popc(m));
        bslot = __shfl_sync(0xFFFFFFFFu, bslot, leader);
        int slot = bslot + rank;
        d_site[slot] = (unsigned short)st;
        d_r1[slot] = r1;
        d_r2[slot] = r2;
    }
    __syncthreads();

    // ---------- load lattice (overlays stamp region) ----------
    for (int i = tid; i < NSITES; i += BLOCK)
        Xs[i] = (unsigned char)(__ldg(&Xw[i]) & 3u);
    const int gmax = min(s_gmax, LMAX);
    __syncthreads();

    // ---------- PHASE 2: wave-ordered execution, both sweeps ----------
    for (int sweep = 0; sweep < NSWEEPS; sweep++) {
        const float* rsel = sweep ? d_r2 : d_r1;
        for (int w = 1; w <= gmax; w++) {
            const int st = s_start[w];
            const int en = s_start[w + 1];
            for (int t = st + tid; t < en; t += BLOCK) {
                const int site = (int)d_site[t];
                const float r  = rsel[t];
                const int u = site >> 8, v = site & 255;
                const int um = (u > 0)   ? u - 1 : 0;
                const int up = (u < 255) ? u + 1 : 255;
                const int vm = (v > 0)   ? v - 1 : 0;
                const int vp = (v < 255) ? v + 1 : 255;
                const int ra = um << 8, rb = u << 8, rc = up << 8;
                unsigned int acc = 0u;     // byte-packed counts of classes 0-2
                acc += 1u << (((unsigned)Xs[ra | vm]) * 8u);
                acc += 1u << (((unsigned)Xs[ra | v ]) * 8u);
                acc += 1u << (((unsigned)Xs[ra | vp]) * 8u);
                acc += 1u << (((unsigned)Xs[rb | vm]) * 8u);
                acc += 1u << (((unsigned)Xs[rb | vp]) * 8u);
                acc += 1u << (((unsigned)Xs[rc | vm]) * 8u);
                acc += 1u << (((unsigned)Xs[rc | v ]) * 8u);
                acc += 1u << (((unsigned)Xs[rc | vp]) * 8u);
                int c0 = (int)(acc & 0xFFu);
                int c1 = (int)((acc >> 8) & 0xFFu);
                int c2 = (int)((acc >> 16) & 0xFFu);
                float4 b = s_B[c0 + 9 * c1 + 81 * c2];
                int x = (b.x < r) + (b.y < r) + (b.z < r) + (b.w < r);
                Xs[site] = (unsigned char)x;
            }
            __syncthreads();   // wave w writes visible before wave w+1 reads
        }
    }

    // ---------- FLOAT32 output ----------
    for (int i = tid; i < NSITES; i += BLOCK)
        out[i] = (float)Xs[i];
}

extern "C" void kernel_launch(void* const* d_in, const int* in_sizes, int n_in,
                              void* d_out, int out_size)
{
    // element-count mapping: 131072 -> uniforms; 65536 x2 -> X_init/perm; 1 -> scalars
    const void* arr64k[2] = {0, 0}; int n64k = 0;
    const void* scal[2]   = {0, 0}; int nsc = 0;
    const void* unif = 0;
    for (int i = 0; i < n_in; i++) {
        int s = in_sizes[i];
        if (s == 131072) unif = d_in[i];
        else if (s == 65536) { if (n64k < 2) arr64k[n64k++] = d_in[i]; }
        else if (s == 1)     { if (nsc  < 2) scal[nsc++]   = d_in[i]; }
    }
    if (!unif || n64k < 2 || nsc < 1) {
        // positional fallback: X_init, perm, uniforms, beta, K
        arr64k[0] = d_in[0];
        arr64k[1] = (n_in > 1) ? d_in[1] : d_in[0];
        unif      = (n_in > 2) ? d_in[2] : d_in[0];
        scal[0]   = (n_in > 3) ? d_in[3] : d_in[0];
        scal[1]   = (n_in > 4) ? d_in[4] : scal[0];
    }
    if (!scal[1]) scal[1] = scal[0];

    const size_t dyn_bytes = 131072 + 65536;   // stamp/X overlay + Lg
    cudaFuncSetAttribute(gibbs_glv,
                         cudaFuncAttributeMaxDynamicSharedMemorySize,
                         (int)dyn_bytes);
    gibbs_glv<<<1, BLOCK, dyn_bytes>>>((const unsigned int*)arr64k[0],
                                       (const unsigned int*)arr64k[1],
                                       (const float*)unif,
                                       (const unsigned int*)scal[0],
                                       (const unsigned int*)scal[1],
                                       (float*)d_out);
}